// round 12
// baseline (speedup 1.0000x reference)
#include <cuda_runtime.h>

#define NN 100000
#define NE 1250000
#define D  64
#define NB 16

// Scratch (no allocs) — g_h/g_deg zeroed every launch via cudaMemsetAsync.
__device__ float  g_h[(size_t)NN * D];     // sum of x[src] per dst node
__device__ float  g_deg[NN];               // in-degree (float)
__device__ float4 g_Wfrag[16 * 32 * 8];    // [kc][lane][tl] = {bH0,bH1,bL0,bL1}
__device__ float  g_bm[D];
__device__ float  g_bs[D];

__device__ __forceinline__ unsigned f2tf(float v) {
    unsigned r;
    asm("cvt.rna.tf32.f32 %0, %1;" : "=r"(r) : "f"(v));
    return r;
}

// ---------------------------------------------------------------------------
// Kernel 1: scatter-add raw x rows (16 threads/edge, float4 vector atomics).
// Block 0 reconstructs W from bases and writes the MMA B-fragment table
// (TF32 hi/lo pre-split, fragment-ordered) — hidden under the ~90us scatter.
// ---------------------------------------------------------------------------
__global__ void k_scatter(const float4* __restrict__ x4, const int* __restrict__ ei,
                          const float* __restrict__ bmw, const float* __restrict__ bmb,
                          const float* __restrict__ bsw, const float* __restrict__ bsb,
                          const float* __restrict__ lc) {
    if (blockIdx.x == 0) {
        __shared__ float c[NB];
        __shared__ float Wc[128][D];   // concat W: rows 0..63 Wm, 64..127 Ws
        if (threadIdx.x < NB) c[threadIdx.x] = lc[threadIdx.x];
        __syncthreads();
        for (int idx = threadIdx.x; idx < D * D; idx += 256) {
            int i = idx >> 6, o = idx & 63;
            float wm = 0.f, ws = 0.f;
            #pragma unroll
            for (int b = 0; b < NB; b++) {
                wm = fmaf(bmw[idx * NB + b], c[b], wm);
                ws = fmaf(bsw[idx * NB + b], c[b], ws);
            }
            Wc[i][o]      = wm;
            Wc[64 + i][o] = ws;
        }
        if (threadIdx.x < D) {
            int o = threadIdx.x;
            float bm = 0.f, bs = 0.f;
            #pragma unroll
            for (int b = 0; b < NB; b++) {
                bm = fmaf(bmb[o * NB + b], c[b], bm);
                bs = fmaf(bsb[o * NB + b], c[b], bs);
            }
            g_bm[o] = bm;
            g_bs[o] = bs;
        }
        __syncthreads();
        // Build fragment table: entry (kc, lane, tl) -> {bH0,bH1,bL0,bL1}
        // with g = lane>>2, t = lane&3:
        //   b0 = W[kc*8 + t][tl*8 + g],  b1 = W[kc*8 + t + 4][tl*8 + g]
        for (int idx = threadIdx.x; idx < 16 * 32 * 8; idx += 256) {
            int tl   = idx & 7;
            int lane = (idx >> 3) & 31;
            int kc   = idx >> 8;
            int g = lane >> 2, t = lane & 3;
            int n  = tl * 8 + g;
            int k0 = kc * 8 + t;
            float w0 = Wc[k0][n];
            float w1 = Wc[k0 + 4][n];
            unsigned h0 = f2tf(w0), h1 = f2tf(w1);
            float4 fr;
            fr.x = __uint_as_float(h0);
            fr.y = __uint_as_float(h1);
            fr.z = __uint_as_float(f2tf(w0 - __uint_as_float(h0)));
            fr.w = __uint_as_float(f2tf(w1 - __uint_as_float(h1)));
            g_Wfrag[idx] = fr;
        }
        return;
    }
    unsigned t = (blockIdx.x - 1) * blockDim.x + threadIdx.x;
    unsigned e = t >> 4;
    if (e >= NE) return;
    int j = t & 15;
    int src = __ldg(ei + e);
    int dst = __ldg(ei + NE + e);
    float4 v = __ldg(x4 + (size_t)src * (D / 4) + j);
    float* p = g_h + (size_t)dst * D + j * 4;
    asm volatile("red.global.add.v4.f32 [%0], {%1,%2,%3,%4};"
                 :: "l"(p), "f"(v.x), "f"(v.y), "f"(v.z), "f"(v.w)
                 : "memory");
    if (j == 0) atomicAdd(&g_deg[dst], 1.0f);
}

// ---------------------------------------------------------------------------
// Kernel 2: out = normalize( h @ Wm + x @ Ws + deg*bm + bs )
// Tensor cores, 3xTF32.  B fragments come pre-split from the gmem fragment
// table via coalesced L1-resident __ldg float4 (no W in smem -> 6 blocks/SM).
// Block = 64 nodes x 64 cols, 128 threads / 4 warps; warp = 16 rows x 64 cols.
// ---------------------------------------------------------------------------
#define IN_STRIDE 132   // 128 + 4 pad (A scalar LDS conflict-free)

#define MMA_TF32(c0,c1,c2,c3, a0,a1,a2,a3, b0,b1)                               \
    asm volatile("mma.sync.aligned.m16n8k8.row.col.f32.tf32.tf32.f32 "          \
                 "{%0,%1,%2,%3}, {%4,%5,%6,%7}, {%8,%9}, {%0,%1,%2,%3};"        \
                 : "+f"(c0), "+f"(c1), "+f"(c2), "+f"(c3)                       \
                 : "r"(a0), "r"(a1), "r"(a2), "r"(a3), "r"(b0), "r"(b1))

__global__ void __launch_bounds__(128, 6)
k_transform(const float* __restrict__ x, float* __restrict__ out) {
    extern __shared__ float smem[];
    float* In   = smem;                     // [64][IN_STRIDE]  concat(h|x)
    float* degS = In + 64 * IN_STRIDE;      // [64]
    float* bmS  = degS + 64;                // [64]
    float* bsS  = bmS + 64;                 // [64]

    int tid  = threadIdx.x;
    int w    = tid >> 5;        // warp 0..3 -> rows w*16 .. w*16+15
    int lane = tid & 31;
    int g    = lane >> 2;       // 0..7
    int t    = lane & 3;        // 0..3
    int n0   = blockIdx.x * 64;

    // --- Prologue: stage inputs into shared ---
    {
        const float4* h4 = (const float4*)g_h;
        const float4* x4 = (const float4*)x;
        for (int i = tid; i < 64 * (D / 4); i += 128) {
            int n = i >> 4, j = i & 15;
            int gn = n0 + n;
            float4 hv = make_float4(0.f, 0.f, 0.f, 0.f);
            float4 xv = hv;
            if (gn < NN) {
                size_t off = (size_t)gn * (D / 4) + j;
                hv = h4[off];
                xv = x4[off];
            }
            *(float4*)&In[n * IN_STRIDE + j * 4]      = hv;
            *(float4*)&In[n * IN_STRIDE + 64 + j * 4] = xv;
        }
    }
    if (tid < 64) {
        int gn = n0 + tid;
        degS[tid] = (gn < NN) ? g_deg[gn] : 0.f;
        bmS[tid]  = g_bm[tid];
        bsS[tid]  = g_bs[tid];
    }
    __syncthreads();

    // --- Main loop: 16 k-chunks of 8; per chunk 8 n-tiles x 3 MMAs ---
    float acc[8][4];
    #pragma unroll
    for (int tl = 0; tl < 8; tl++)
        #pragma unroll
        for (int j = 0; j < 4; j++) acc[tl][j] = 0.f;

    const int rowA = w * 16 + g;
    const float* aRow0 = &In[rowA * IN_STRIDE];
    const float* aRow1 = &In[(rowA + 8) * IN_STRIDE];
    const float4* fw = g_Wfrag + lane * 8;   // + kc*256 + tl

    #pragma unroll 4
    for (int kc = 0; kc < 16; kc++) {
        int kb = kc * 8;
        // A fragment (rows g, g+8; cols t, t+4), on-the-fly hi/lo split
        float fa0 = aRow0[kb + t];
        float fa1 = aRow1[kb + t];
        float fa2 = aRow0[kb + t + 4];
        float fa3 = aRow1[kb + t + 4];
        unsigned aH0 = f2tf(fa0), aH1 = f2tf(fa1), aH2 = f2tf(fa2), aH3 = f2tf(fa3);
        unsigned aL0 = f2tf(fa0 - __uint_as_float(aH0));
        unsigned aL1 = f2tf(fa1 - __uint_as_float(aH1));
        unsigned aL2 = f2tf(fa2 - __uint_as_float(aH2));
        unsigned aL3 = f2tf(fa3 - __uint_as_float(aH3));

        const float4* fk = fw + kc * 256;
        #pragma unroll
        for (int tl = 0; tl < 8; tl++) {
            float4 b = __ldg(fk + tl);
            unsigned bH0 = __float_as_uint(b.x);
            unsigned bH1 = __float_as_uint(b.y);
            unsigned bL0 = __float_as_uint(b.z);
            unsigned bL1 = __float_as_uint(b.w);
            MMA_TF32(acc[tl][0], acc[tl][1], acc[tl][2], acc[tl][3],
                     aH0, aH1, aH2, aH3, bH0, bH1);
            MMA_TF32(acc[tl][0], acc[tl][1], acc[tl][2], acc[tl][3],
                     aH0, aH1, aH2, aH3, bL0, bL1);
            MMA_TF32(acc[tl][0], acc[tl][1], acc[tl][2], acc[tl][3],
                     aL0, aL1, aL2, aL3, bH0, bH1);
        }
    }

    // --- Epilogue: bias + deg*bm, L2 norm across quad lanes, store ---
    float dg0 = degS[rowA];
    float dg1 = degS[rowA + 8];
    float ss0 = 0.f, ss1 = 0.f;
    #pragma unroll
    for (int tl = 0; tl < 8; tl++) {
        int c0 = tl * 8 + 2 * t;
        float bm0 = bmS[c0], bm1 = bmS[c0 + 1];
        float bs0 = bsS[c0], bs1 = bsS[c0 + 1];
        float v00 = acc[tl][0] + dg0 * bm0 + bs0;
        float v01 = acc[tl][1] + dg0 * bm1 + bs1;
        float v10 = acc[tl][2] + dg1 * bm0 + bs0;
        float v11 = acc[tl][3] + dg1 * bm1 + bs1;
        acc[tl][0] = v00; acc[tl][1] = v01; acc[tl][2] = v10; acc[tl][3] = v11;
        ss0 = fmaf(v00, v00, fmaf(v01, v01, ss0));
        ss1 = fmaf(v10, v10, fmaf(v11, v11, ss1));
    }
    ss0 += __shfl_xor_sync(0xffffffffu, ss0, 1);
    ss0 += __shfl_xor_sync(0xffffffffu, ss0, 2);
    ss1 += __shfl_xor_sync(0xffffffffu, ss1, 1);
    ss1 += __shfl_xor_sync(0xffffffffu, ss1, 2);
    float f0 = 1.f / fmaxf(sqrtf(ss0), 1e-12f);
    float f1 = 1.f / fmaxf(sqrtf(ss1), 1e-12f);

    int gn0 = n0 + rowA;
    int gn1 = gn0 + 8;
    #pragma unroll
    for (int tl = 0; tl < 8; tl++) {
        int c0 = tl * 8 + 2 * t;
        if (gn0 < NN)
            *(float2*)&out[(size_t)gn0 * D + c0] = make_float2(acc[tl][0] * f0, acc[tl][1] * f0);
        if (gn1 < NN)
            *(float2*)&out[(size_t)gn1 * D + c0] = make_float2(acc[tl][2] * f1, acc[tl][3] * f1);
    }
}

#define SMEM_BYTES ((64 * IN_STRIDE + 64 * 3) * (int)sizeof(float))

extern "C" void kernel_launch(void* const* d_in, const int* in_sizes, int n_in,
                              void* d_out, int out_size) {
    const float* x   = (const float*)d_in[0];
    const int*   ei  = (const int*)d_in[1];
    const float* bmw = (const float*)d_in[2];
    const float* bmb = (const float*)d_in[3];
    const float* bsw = (const float*)d_in[4];
    const float* bsb = (const float*)d_in[5];
    const float* lc  = (const float*)d_in[6];
    float* out = (float*)d_out;

    void* hptr = nullptr;
    void* dptr = nullptr;
    cudaGetSymbolAddress(&hptr, g_h);
    cudaGetSymbolAddress(&dptr, g_deg);
    cudaMemsetAsync(hptr, 0, sizeof(float) * (size_t)NN * D);
    cudaMemsetAsync(dptr, 0, sizeof(float) * NN);

    unsigned total = (unsigned)NE * 16u;
    k_scatter<<<(total + 255u) / 256u + 1u, 256>>>((const float4*)x, ei, bmw, bmb, bsw, bsb, lc);

    k_transform<<<(NN + 63) / 64, 128, SMEM_BYTES>>>(x, out);
}

// round 13
// speedup vs baseline: 1.3165x; 1.3165x over previous
#include <cuda_runtime.h>

#define NN 100000
#define NE 1250000
#define D  64
#define NB 16
#define EPW 256
#define NWARP ((NE + EPW - 1) / EPW)      // 4883 warps
#define AGG_BLKS ((NWARP + 7) / 8)        // 611 blocks of 8 warps
#define SELF_TILES ((NN + 63) / 64)       // 1563
#define SCAN_B ((NN + 255) / 256)         // 391

// Scratch (no allocs). Invariants at entry of every launch (zero at module
// load, restored by the pipeline itself each call):
//   g_cnt == 0   (k_scan re-zeroes after reading)
//   g_pos2 == 0  (k_final re-zeroes)
//   g_done == 0  (k_scan last block resets)
__device__ float    g_h[(size_t)NN * D];
__device__ int      g_cnt[NN];
__device__ int      g_loc[NN];        // per-chunk exclusive scan
__device__ int      g_offF[NN + 1];   // final CSR offsets
__device__ int      g_pos2[NN];       // fill placement counters
__device__ int      g_blk[512];
__device__ int      g_blkpref[512];
__device__ unsigned g_done;
__device__ int      g_srcs[NE + 64];
__device__ float    g_Wm[D * D];
__device__ float    g_Ws[D * D];
__device__ float    g_bm[D];
__device__ float    g_bs[D];

// ---------------------------------------------------------------------------
// 1) dst histogram; block 0 also reconstructs weights from bases
// ---------------------------------------------------------------------------
__global__ void k_hist(const int* __restrict__ ei,
                       const float* __restrict__ bmw, const float* __restrict__ bmb,
                       const float* __restrict__ bsw, const float* __restrict__ bsb,
                       const float* __restrict__ lc) {
    if (blockIdx.x == 0) {
        __shared__ float c[NB];
        if (threadIdx.x < NB) c[threadIdx.x] = lc[threadIdx.x];
        __syncthreads();
        for (int idx = threadIdx.x; idx < D * D; idx += 256) {
            float wm = 0.f, ws = 0.f;
            #pragma unroll
            for (int b = 0; b < NB; b++) {
                wm = fmaf(bmw[idx * NB + b], c[b], wm);
                ws = fmaf(bsw[idx * NB + b], c[b], ws);
            }
            g_Wm[idx] = wm;
            g_Ws[idx] = ws;
        }
        if (threadIdx.x < D) {
            int o = threadIdx.x;
            float bm = 0.f, bs = 0.f;
            #pragma unroll
            for (int b = 0; b < NB; b++) {
                bm = fmaf(bmb[o * NB + b], c[b], bm);
                bs = fmaf(bsb[o * NB + b], c[b], bs);
            }
            g_bm[o] = bm;
            g_bs[o] = bs;
        }
        return;
    }
    unsigned e = (blockIdx.x - 1) * 256u + threadIdx.x;
    if (e < NE) atomicAdd(&g_cnt[__ldg(ei + NE + e)], 1);
}

// ---------------------------------------------------------------------------
// 2) single-launch scan: per-chunk exclusive scan, last block scans the
//    chunk totals.  Self-cleans g_cnt and g_done.
// ---------------------------------------------------------------------------
__global__ void k_scan() {
    __shared__ int s[512];
    __shared__ int isLast;
    int t = threadIdx.x;
    int b = blockIdx.x;
    int i = b * 256 + t;
    int v = (i < NN) ? g_cnt[i] : 0;
    s[t] = v;
    __syncthreads();
    #pragma unroll
    for (int d = 1; d < 256; d <<= 1) {
        int u = (t >= d) ? s[t - d] : 0;
        __syncthreads();
        s[t] += u;
        __syncthreads();
    }
    if (i < NN) {
        g_loc[i] = s[t] - v;
        g_cnt[i] = 0;                       // self-clean
    }
    if (t == 255) g_blk[b] = s[255];
    __threadfence();
    __syncthreads();
    if (t == 0) {
        unsigned old = atomicAdd(&g_done, 1u);
        isLast = (old == gridDim.x - 1) ? 1 : 0;
    }
    __syncthreads();
    if (isLast) {
        int v0 = (t < SCAN_B) ? g_blk[t] : 0;
        int v1 = (t + 256 < SCAN_B) ? g_blk[t + 256] : 0;
        s[t] = v0;
        s[t + 256] = v1;
        __syncthreads();
        #pragma unroll
        for (int d = 1; d < 512; d <<= 1) {
            int u0 = (t >= d) ? s[t - d] : 0;
            int u1 = (t + 256 >= d) ? s[t + 256 - d] : 0;
            __syncthreads();
            s[t] += u0;
            s[t + 256] += u1;
            __syncthreads();
        }
        if (t < SCAN_B) g_blkpref[t] = s[t] - v0;
        if (t + 256 < SCAN_B) g_blkpref[t + 256] = s[t + 256] - v1;
        if (t == 0) g_done = 0;             // self-clean
    }
}

// ---------------------------------------------------------------------------
// 3) counting-sort fill of src list + materialize final offsets
// ---------------------------------------------------------------------------
__global__ void k_fill(const int* __restrict__ ei) {
    int t = threadIdx.x;
    unsigned b = blockIdx.x;
    int i = (int)(b * 256u) + t;
    if (b < SCAN_B && i < NN) g_offF[i] = g_loc[i] + g_blkpref[b];
    if (i == 0) g_offF[NN] = NE;
    unsigned e = b * 256u + t;
    if (e < NE) {
        int d   = __ldg(ei + NE + e);
        int src = __ldg(ei + e);
        int base = __ldg(&g_loc[d]) + __ldg(&g_blkpref[d >> 8]);
        int p = atomicAdd(&g_pos2[d], 1);
        g_srcs[base + p] = src;
    }
}

// ---------------------------------------------------------------------------
// 4) aggregation (warp per 256-edge range, ST-only, owns nodes by first edge)
//    + self-GEMM tiles (out = x @ Ws + bs) overlapping in the same grid.
// ---------------------------------------------------------------------------
#define ST68 68

__global__ void __launch_bounds__(256)
k_agg(const float2* __restrict__ x2, const float* __restrict__ x,
      float* __restrict__ out) {
    if (blockIdx.x < AGG_BLKS) {
        int wid = blockIdx.x * 8 + (threadIdx.x >> 5);
        if (wid >= NWARP) return;
        int l = threadIdx.x & 31;
        int e0 = wid * EPW;
        int e1 = min(e0 + EPW, NE);
        // lower_bound: first n with offF[n] >= e0
        int lo = 0, hi = NN;
        while (lo < hi) {
            int mid = (lo + hi) >> 1;
            if (__ldg(&g_offF[mid]) < e0) lo = mid + 1;
            else hi = mid;
        }
        int n = lo;
        while (n < NN) {
            int s = __ldg(&g_offF[n]);
            if (s >= e1) break;
            int t = __ldg(&g_offF[n + 1]);
            float2 acc = make_float2(0.f, 0.f);
            int e = s;
            for (; e + 4 <= t; e += 4) {
                int s0 = __ldg(g_srcs + e);
                int s1 = __ldg(g_srcs + e + 1);
                int s2 = __ldg(g_srcs + e + 2);
                int s3 = __ldg(g_srcs + e + 3);
                float2 v0 = __ldg(x2 + (size_t)s0 * 32 + l);
                float2 v1 = __ldg(x2 + (size_t)s1 * 32 + l);
                float2 v2 = __ldg(x2 + (size_t)s2 * 32 + l);
                float2 v3 = __ldg(x2 + (size_t)s3 * 32 + l);
                acc.x += v0.x + v1.x + v2.x + v3.x;
                acc.y += v0.y + v1.y + v2.y + v3.y;
            }
            for (; e < t; e++) {
                int s0 = __ldg(g_srcs + e);
                float2 v0 = __ldg(x2 + (size_t)s0 * 32 + l);
                acc.x += v0.x;
                acc.y += v0.y;
            }
            ((float2*)g_h)[(size_t)n * 32 + l] = acc;   // plain ST, sole owner
            n++;
        }
        return;
    }
    // ---- self-GEMM tile: out = x @ Ws + bs (64 nodes x 64 cols) ----
    __shared__ float In[64 * ST68];
    __shared__ float Wsh[64 * 64];
    int tile = blockIdx.x - AGG_BLKS;
    int tid = threadIdx.x;
    int n0 = tile * 64;
    {
        const float4* ws4 = (const float4*)g_Ws;
        float4* w4 = (float4*)Wsh;
        for (int i = tid; i < (D * D) / 4; i += 256) w4[i] = ws4[i];
    }
    {
        const float4* x4 = (const float4*)x;
        for (int i = tid; i < 64 * (D / 4); i += 256) {
            int n = i >> 4, j = i & 15;
            int gn = n0 + n;
            float4 v = make_float4(0.f, 0.f, 0.f, 0.f);
            if (gn < NN) v = x4[(size_t)gn * (D / 4) + j];
            *(float4*)&In[n * ST68 + j * 4] = v;
        }
    }
    __syncthreads();
    int to = tid & 15;
    int tn = tid >> 4;
    float acc[4][4];
    #pragma unroll
    for (int r = 0; r < 4; r++)
        #pragma unroll
        for (int c = 0; c < 4; c++) acc[r][c] = 0.f;
    const float* a0 = &In[(tn * 4 + 0) * ST68];
    const float* a1 = &In[(tn * 4 + 1) * ST68];
    const float* a2 = &In[(tn * 4 + 2) * ST68];
    const float* a3 = &In[(tn * 4 + 3) * ST68];
    #pragma unroll 8
    for (int k = 0; k < 64; k++) {
        float4 b = *(const float4*)&Wsh[k * 64 + to * 4];
        float v0 = a0[k], v1 = a1[k], v2 = a2[k], v3 = a3[k];
        acc[0][0] = fmaf(v0, b.x, acc[0][0]); acc[0][1] = fmaf(v0, b.y, acc[0][1]);
        acc[0][2] = fmaf(v0, b.z, acc[0][2]); acc[0][3] = fmaf(v0, b.w, acc[0][3]);
        acc[1][0] = fmaf(v1, b.x, acc[1][0]); acc[1][1] = fmaf(v1, b.y, acc[1][1]);
        acc[1][2] = fmaf(v1, b.z, acc[1][2]); acc[1][3] = fmaf(v1, b.w, acc[1][3]);
        acc[2][0] = fmaf(v2, b.x, acc[2][0]); acc[2][1] = fmaf(v2, b.y, acc[2][1]);
        acc[2][2] = fmaf(v2, b.z, acc[2][2]); acc[2][3] = fmaf(v2, b.w, acc[2][3]);
        acc[3][0] = fmaf(v3, b.x, acc[3][0]); acc[3][1] = fmaf(v3, b.y, acc[3][1]);
        acc[3][2] = fmaf(v3, b.z, acc[3][2]); acc[3][3] = fmaf(v3, b.w, acc[3][3]);
    }
    float bsv[4];
    #pragma unroll
    for (int c = 0; c < 4; c++) bsv[c] = g_bs[to * 4 + c];
    #pragma unroll
    for (int r = 0; r < 4; r++) {
        int gn = n0 + tn * 4 + r;
        if (gn < NN) {
            float4 o4 = make_float4(acc[r][0] + bsv[0], acc[r][1] + bsv[1],
                                    acc[r][2] + bsv[2], acc[r][3] + bsv[3]);
            *(float4*)&out[(size_t)gn * D + to * 4] = o4;
        }
    }
}

// ---------------------------------------------------------------------------
// 5) final: out = normalize( h @ Wm + out_prev + deg*bm ).  Self-cleans g_pos2.
// ---------------------------------------------------------------------------
__global__ void __launch_bounds__(256)
k_final(float* __restrict__ out) {
    __shared__ float In[64 * ST68];
    __shared__ float Wsh[64 * 64];
    __shared__ float red[64 * 17];
    __shared__ float nf[64];
    __shared__ float degS[64];

    int tid = threadIdx.x;
    int n0 = blockIdx.x * 64;

    if (tid < 64) {
        int gn = n0 + tid;
        float dg = 0.f;
        if (gn < NN) {
            int s = __ldg(&g_offF[gn]);
            int t = __ldg(&g_offF[gn + 1]);
            dg = (float)(t - s);
            g_pos2[gn] = 0;                 // self-clean for next launch
        }
        degS[tid] = dg;
    }
    {
        const float4* wm4 = (const float4*)g_Wm;
        float4* w4 = (float4*)Wsh;
        for (int i = tid; i < (D * D) / 4; i += 256) w4[i] = wm4[i];
    }
    __syncthreads();
    {
        const float4* h4 = (const float4*)g_h;
        for (int i = tid; i < 64 * (D / 4); i += 256) {
            int n = i >> 4, j = i & 15;
            int gn = n0 + n;
            float4 v = make_float4(0.f, 0.f, 0.f, 0.f);
            if (gn < NN && degS[n] > 0.f)     // deg==0 -> h is stale, treat as 0
                v = h4[(size_t)gn * (D / 4) + j];
            *(float4*)&In[n * ST68 + j * 4] = v;
        }
    }
    __syncthreads();

    int to = tid & 15;
    int tn = tid >> 4;
    float acc[4][4];
    #pragma unroll
    for (int r = 0; r < 4; r++)
        #pragma unroll
        for (int c = 0; c < 4; c++) acc[r][c] = 0.f;
    const float* a0 = &In[(tn * 4 + 0) * ST68];
    const float* a1 = &In[(tn * 4 + 1) * ST68];
    const float* a2 = &In[(tn * 4 + 2) * ST68];
    const float* a3 = &In[(tn * 4 + 3) * ST68];
    #pragma unroll 8
    for (int k = 0; k < 64; k++) {
        float4 b = *(const float4*)&Wsh[k * 64 + to * 4];
        float v0 = a0[k], v1 = a1[k], v2 = a2[k], v3 = a3[k];
        acc[0][0] = fmaf(v0, b.x, acc[0][0]); acc[0][1] = fmaf(v0, b.y, acc[0][1]);
        acc[0][2] = fmaf(v0, b.z, acc[0][2]); acc[0][3] = fmaf(v0, b.w, acc[0][3]);
        acc[1][0] = fmaf(v1, b.x, acc[1][0]); acc[1][1] = fmaf(v1, b.y, acc[1][1]);
        acc[1][2] = fmaf(v1, b.z, acc[1][2]); acc[1][3] = fmaf(v1, b.w, acc[1][3]);
        acc[2][0] = fmaf(v2, b.x, acc[2][0]); acc[2][1] = fmaf(v2, b.y, acc[2][1]);
        acc[2][2] = fmaf(v2, b.z, acc[2][2]); acc[2][3] = fmaf(v2, b.w, acc[2][3]);
        acc[3][0] = fmaf(v3, b.x, acc[3][0]); acc[3][1] = fmaf(v3, b.y, acc[3][1]);
        acc[3][2] = fmaf(v3, b.z, acc[3][2]); acc[3][3] = fmaf(v3, b.w, acc[3][3]);
    }

    float bmv[4];
    #pragma unroll
    for (int c = 0; c < 4; c++) bmv[c] = g_bm[to * 4 + c];

    float vals[4][4];
    #pragma unroll
    for (int r = 0; r < 4; r++) {
        int gn = n0 + tn * 4 + r;
        float dg = degS[tn * 4 + r];
        float ss = 0.f;
        float4 prev = make_float4(0.f, 0.f, 0.f, 0.f);
        if (gn < NN) prev = *(const float4*)&out[(size_t)gn * D + to * 4];
        float pv[4] = {prev.x, prev.y, prev.z, prev.w};
        #pragma unroll
        for (int c = 0; c < 4; c++) {
            float v = acc[r][c] + pv[c] + dg * bmv[c];
            vals[r][c] = v;
            ss = fmaf(v, v, ss);
        }
        red[(tn * 4 + r) * 17 + to] = ss;
    }
    __syncthreads();

    if (tid < 64) {
        float s = 0.f;
        #pragma unroll
        for (int t2 = 0; t2 < 16; t2++) s += red[tid * 17 + t2];
        nf[tid] = 1.f / fmaxf(sqrtf(s), 1e-12f);
    }
    __syncthreads();

    #pragma unroll
    for (int r = 0; r < 4; r++) {
        int gn = n0 + tn * 4 + r;
        if (gn < NN) {
            float f = nf[tn * 4 + r];
            float4 o4 = make_float4(vals[r][0] * f, vals[r][1] * f,
                                    vals[r][2] * f, vals[r][3] * f);
            *(float4*)&out[(size_t)gn * D + to * 4] = o4;
        }
    }
}

extern "C" void kernel_launch(void* const* d_in, const int* in_sizes, int n_in,
                              void* d_out, int out_size) {
    const float* x   = (const float*)d_in[0];
    const int*   ei  = (const int*)d_in[1];
    const float* bmw = (const float*)d_in[2];
    const float* bmb = (const float*)d_in[3];
    const float* bsw = (const float*)d_in[4];
    const float* bsb = (const float*)d_in[5];
    const float* lc  = (const float*)d_in[6];
    float* out = (float*)d_out;

    unsigned ehblk = (NE + 255u) / 256u;            // 4883
    k_hist<<<ehblk + 1, 256>>>(ei, bmw, bmb, bsw, bsb, lc);
    k_scan<<<SCAN_B, 256>>>();
    k_fill<<<ehblk, 256>>>(ei);
    k_agg<<<AGG_BLKS + SELF_TILES, 256>>>((const float2*)x, x, out);
    k_final<<<SELF_TILES, 256>>>(out);
}